// round 5
// baseline (speedup 1.0000x reference)
#include <cuda_runtime.h>

// LSTM_74122545594502: 3-layer bidirectional LSTM, B=4096 T=256 D=4 H=16.
// Round 5: warp-synchronous, one warp = 4 chains. f32x2 packs the GATE-ROW
// pair (l, l+32): lane l accumulates (i_l, g_l), lane l+16 accumulates
// (f_l, o_l) per chain. Weights stored pre-paired in smem -> LDS.128 feeds
// FFMA2 directly, zero in-loop packing. Inputs (x, h) stored duplicated
// (v,v) in smem; broadcast LDS.128. Update via one bfly(16) exchange.

namespace {
constexpr int B_ = 4096;
constexpr int T_ = 256;
constexpr int D_ = 4;
constexpr int H_ = 16;
constexpr int NB = 4;                  // chains per warp
constexpr int WPC = 4;                 // warps per CTA
constexpr int NCTA = 2 * (B_ / NB) / WPC;  // 512
}

typedef unsigned long long ull;

__device__ __forceinline__ ull pack2(float x, float y) {
    ull r;
    asm("mov.b64 %0, {%1, %2};" : "=l"(r) : "f"(x), "f"(y));
    return r;
}
__device__ __forceinline__ void unpack2(ull v, float& x, float& y) {
    asm("mov.b64 {%0, %1}, %2;" : "=f"(x), "=f"(y) : "l"(v));
}
__device__ __forceinline__ ull ffma2(ull a, ull b, ull c) {
    ull d;
    asm("fma.rn.f32x2 %0, %1, %2, %3;" : "=l"(d) : "l"(a), "l"(b), "l"(c));
    return d;
}

// sigmoid(v) = 1/(1+exp(-v)); tanh(v) = 2*sigmoid(2v)-1.
__device__ __forceinline__ float fast_act(float v, bool is_tanh) {
    float arg = is_tanh ? (-2.0f * v) : (-v);
    float e = __expf(arg);
    float r = __fdividef(1.0f, 1.0f + e);
    return is_tanh ? (2.0f * r - 1.0f) : r;
}
__device__ __forceinline__ float fast_tanh(float v) { return fast_act(v, true); }

struct Params {
    const float* y;
    const float* w[24];  // dir*12 + {Wih1,Whh1,bih1,bhh1, Wih2,...,bhh3}
};

__device__ float g_h3[2][B_][H_];  // final layer-3 h

// 4 FFMA2 for one input index j: wp = (W[r0][j], W[r1][j]); inputs duplicated.
__device__ __forceinline__ void jstep(ull wp, const float* in_j,
                                      ull& a0, ull& a1, ull& a2, ull& a3) {
    ulonglong2 P = *(const ulonglong2*)(in_j);      // (v0,v0),(v1,v1)
    ulonglong2 Q = *(const ulonglong2*)(in_j + 4);  // (v2,v2),(v3,v3)
    a0 = ffma2(wp, P.x, a0);
    a1 = ffma2(wp, P.y, a1);
    a2 = ffma2(wp, Q.x, a2);
    a3 = ffma2(wp, Q.y, a3);
}

// Activate, bfly(16) exchange, c/h update for this lane's 2 chains.
// Returns packed (h for chain cA, h for chain cB); stores duplicated 16B.
__device__ __forceinline__ ull do_update(ull a0, ull a1, ull a2, ull a3,
                                         bool low, float& cA, float& cB,
                                         float* hdst) {
    float l0, h0_, l1, h1_, l2, h2_, l3, h3_;
    unpack2(a0, l0, h0_); unpack2(a1, l1, h1_);
    unpack2(a2, l2, h2_); unpack2(a3, l3, h3_);
    // lo halves (rows 0-31): always sigmoid. hi halves: g(tanh) on low lanes,
    // o(sigmoid) on high lanes.
    l0 = fast_act(l0, false); l1 = fast_act(l1, false);
    l2 = fast_act(l2, false); l3 = fast_act(l3, false);
    h0_ = fast_act(h0_, low); h1_ = fast_act(h1_, low);
    h2_ = fast_act(h2_, low); h3_ = fast_act(h3_, low);
    ull A0 = pack2(l0, h0_), A1 = pack2(l1, h1_);
    ull A2 = pack2(l2, h2_), A3 = pack2(l3, h3_);
    // low sends chains 2,3 (i,g); high sends chains 0,1 (f,o).
    ull sA = low ? A2 : A0;
    ull sB = low ? A3 : A1;
    ull rA = __shfl_xor_sync(0xffffffffu, sA, 16);
    ull rB = __shfl_xor_sync(0xffffffffu, sB, 16);
    ull IG0 = low ? A0 : rA;   // (i,g) for chain (low?0:2)
    ull FO0 = low ? rA : A2;   // (f,o) same chain
    ull IG1 = low ? A1 : rB;   // chain (low?1:3)
    ull FO1 = low ? rB : A3;
    float i0, g0, f0, o0, i1, g1, f1, o1;
    unpack2(IG0, i0, g0); unpack2(FO0, f0, o0);
    unpack2(IG1, i1, g1); unpack2(FO1, f1, o1);
    cA = fmaf(f0, cA, i0 * g0);
    cB = fmaf(f1, cB, i1 * g1);
    float ha = o0 * fast_tanh(cA);
    float hb = o1 * fast_tanh(cB);
    *(float4*)hdst = make_float4(ha, ha, hb, hb);
    return pack2(ha, hb);
}

__global__ void __launch_bounds__(128, 4) lstm_kernel(Params p) {
    // Weight table: [layer(2)][jpair(16)][lane(32)] float4 =
    //   (W[r0][2jp], W[r1][2jp], W[r0][2jp+1], W[r1][2jp+1]),
    //   j in [0,16)=ih rows, [16,32)=hh rows. 16 KB.
    __shared__ float4 wtab[2][16][32];
    __shared__ __align__(16) float xsm[WPC][2][D_][8];       // duplicated x
    __shared__ __align__(16) float hsm[WPC][3][2][H_][8];    // duplicated h

    const int tid  = threadIdx.x;
    const int lane = tid & 31;
    const int w    = tid >> 5;
    const int dir  = blockIdx.x >> 8;
    const int gidx = (blockIdx.x & 255) * WPC + w;
    const int b0   = gidx * NB;
    const bool low = lane < 16;
    const int unit = lane & 15;

    const float* const* ws = &p.w[dir * 12];

    // ---- cooperative fill of L2/L3 packed weight table ----
    for (int e = tid; e < 2 * 16 * 32; e += 128) {
        int L = e >> 9, rem = e & 511, jp = rem >> 5, ln = rem & 31;
        int r0e = ln, r1e = ln + 32;
        int j0 = 2 * jp, j1 = 2 * jp + 1;
        const float* wih = ws[4 + 4 * L];
        const float* whh = ws[5 + 4 * L];
        float v00 = (j0 < 16) ? wih[r0e * 16 + j0] : whh[r0e * 16 + j0 - 16];
        float v01 = (j0 < 16) ? wih[r1e * 16 + j0] : whh[r1e * 16 + j0 - 16];
        float v10 = (j1 < 16) ? wih[r0e * 16 + j1] : whh[r0e * 16 + j1 - 16];
        float v11 = (j1 < 16) ? wih[r1e * 16 + j1] : whh[r1e * 16 + j1 - 16];
        wtab[L][jp][ln] = make_float4(v00, v01, v10, v11);
    }

    // ---- L1 weights pre-packed in registers; biases packed ----
    const int r0 = lane, r1 = lane + 32;
    ull wl1[D_ + H_];
#pragma unroll
    for (int j = 0; j < D_; ++j)
        wl1[j] = pack2(ws[0][r0 * D_ + j], ws[0][r1 * D_ + j]);
#pragma unroll
    for (int j = 0; j < H_; ++j)
        wl1[D_ + j] = pack2(ws[1][r0 * H_ + j], ws[1][r1 * H_ + j]);
    const ull bp1 = pack2(ws[2][r0] + ws[3][r0], ws[2][r1] + ws[3][r1]);
    const ull bp2 = pack2(ws[6][r0] + ws[7][r0], ws[6][r1] + ws[7][r1]);
    const ull bp3 = pack2(ws[10][r0] + ws[11][r0], ws[10][r1] + ws[11][r1]);

    // ---- init h (buf 0) and x (buf 0) ----
    if (low) {
        float4 z = make_float4(0.f, 0.f, 0.f, 0.f);
        hsm4init:
        *(float4*)&hsm[w][0][0][unit][0] = z;
        *(float4*)&hsm[w][0][0][unit][4] = z;
        *(float4*)&hsm[w][1][0][unit][0] = z;
        *(float4*)&hsm[w][1][0][unit][4] = z;
        *(float4*)&hsm[w][2][0][unit][0] = z;
        *(float4*)&hsm[w][2][0][unit][4] = z;
        int c = lane & 3, j = lane >> 2;
        int tt = dir ? (T_ - 1) : 0;
        float v = p.y[((size_t)(b0 + c) * T_ + tt) * D_ + j];
        *(ull*)&xsm[w][0][j][2 * c] = pack2(v, v);
    }
    __syncthreads();  // weight table + init visible

    float c1A = 0.f, c1B = 0.f, c2A = 0.f, c2B = 0.f, c3A = 0.f, c3B = 0.f;
    ull h3out = 0ull;
    const int xc = lane & 3, xj = lane >> 2;

#pragma unroll 1
    for (int step = 0; step < T_; ++step) {
        const int buf = step & 1, nbuf = buf ^ 1;

        // early next-x load (latency hidden under L1 gates)
        float xn = 0.0f;
        if (low && step + 1 < T_) {
            int tt = dir ? (T_ - 2 - step) : (step + 1);
            xn = p.y[((size_t)(b0 + xc) * T_ + tt) * D_ + xj];
        }

        // ---------------- layer 1 (register weights) ----------------
        {
            ull a0 = bp1, a1 = bp1, a2 = bp1, a3 = bp1;
            const float* xin = &xsm[w][buf][0][0];
#pragma unroll
            for (int j = 0; j < D_; ++j)
                jstep(wl1[j], xin + 8 * j, a0, a1, a2, a3);
            const float* hin = &hsm[w][0][buf][0][0];
#pragma unroll
            for (int j = 0; j < H_; ++j)
                jstep(wl1[D_ + j], hin + 8 * j, a0, a1, a2, a3);
            float* hd = &hsm[w][0][nbuf][unit][0] + (low ? 0 : 4);
            do_update(a0, a1, a2, a3, low, c1A, c1B, hd);
        }
        if (low && step + 1 < T_) *(ull*)&xsm[w][nbuf][xj][2 * xc] = pack2(xn, xn);
        __syncwarp();

        // ---------------- layer 2 (smem weights) ----------------
        {
            ull a0 = bp2, a1 = bp2, a2 = bp2, a3 = bp2;
            const float* inA = &hsm[w][0][nbuf][0][0];  // fresh L1 h
            const float* inB = &hsm[w][1][buf][0][0];   // own old h
#pragma unroll
            for (int jp = 0; jp < 8; ++jp) {
                ulonglong2 wv = *(const ulonglong2*)&wtab[0][jp][lane];
                jstep(wv.x, inA + 8 * (2 * jp), a0, a1, a2, a3);
                jstep(wv.y, inA + 8 * (2 * jp + 1), a0, a1, a2, a3);
            }
#pragma unroll
            for (int jp = 8; jp < 16; ++jp) {
                ulonglong2 wv = *(const ulonglong2*)&wtab[0][jp][lane];
                jstep(wv.x, inB + 8 * (2 * jp - 16), a0, a1, a2, a3);
                jstep(wv.y, inB + 8 * (2 * jp - 15), a0, a1, a2, a3);
            }
            float* hd = &hsm[w][1][nbuf][unit][0] + (low ? 0 : 4);
            do_update(a0, a1, a2, a3, low, c2A, c2B, hd);
        }
        __syncwarp();

        // ---------------- layer 3 (smem weights) ----------------
        {
            ull a0 = bp3, a1 = bp3, a2 = bp3, a3 = bp3;
            const float* inA = &hsm[w][1][nbuf][0][0];  // fresh L2 h
            const float* inB = &hsm[w][2][buf][0][0];   // own old h
#pragma unroll
            for (int jp = 0; jp < 8; ++jp) {
                ulonglong2 wv = *(const ulonglong2*)&wtab[1][jp][lane];
                jstep(wv.x, inA + 8 * (2 * jp), a0, a1, a2, a3);
                jstep(wv.y, inA + 8 * (2 * jp + 1), a0, a1, a2, a3);
            }
#pragma unroll
            for (int jp = 8; jp < 16; ++jp) {
                ulonglong2 wv = *(const ulonglong2*)&wtab[1][jp][lane];
                jstep(wv.x, inB + 8 * (2 * jp - 16), a0, a1, a2, a3);
                jstep(wv.y, inB + 8 * (2 * jp - 15), a0, a1, a2, a3);
            }
            float* hd = &hsm[w][2][nbuf][unit][0] + (low ? 0 : 4);
            h3out = do_update(a0, a1, a2, a3, low, c3A, c3B, hd);
        }
        __syncwarp();
    }

    // final layer-3 h: low lane -> chains 0,1; high lane -> chains 2,3.
    {
        float ha, hb;
        unpack2(h3out, ha, hb);
        int c = low ? 0 : 2;
        g_h3[dir][b0 + c][unit]     = ha;
        g_h3[dir][b0 + c + 1][unit] = hb;
    }
}

// out[b,k] = b_out[k] + sum_j W_out[k][j]*hf3[b][j] + W_out[k][16+j]*hb3[b][j]
__global__ void proj_kernel(const float* __restrict__ Wo,
                            const float* __restrict__ bo,
                            float* __restrict__ out) {
    int b = blockIdx.x * blockDim.x + threadIdx.x;
    if (b >= B_) return;
    float a0 = bo[0], a1 = bo[1], a2 = bo[2], a3 = bo[3];
#pragma unroll
    for (int j = 0; j < H_; ++j) {
        float hf = g_h3[0][b][j];
        a0 += Wo[0 * 32 + j] * hf;
        a1 += Wo[1 * 32 + j] * hf;
        a2 += Wo[2 * 32 + j] * hf;
        a3 += Wo[3 * 32 + j] * hf;
    }
#pragma unroll
    for (int j = 0; j < H_; ++j) {
        float hb = g_h3[1][b][j];
        a0 += Wo[0 * 32 + 16 + j] * hb;
        a1 += Wo[1 * 32 + 16 + j] * hb;
        a2 += Wo[2 * 32 + 16 + j] * hb;
        a3 += Wo[3 * 32 + 16 + j] * hb;
    }
    ((float4*)out)[b] = make_float4(a0, a1, a2, a3);
}

extern "C" void kernel_launch(void* const* d_in, const int* in_sizes, int n_in,
                              void* d_out, int out_size) {
    (void)in_sizes; (void)n_in; (void)out_size;
    Params p;
    p.y = (const float*)d_in[0];
    for (int i = 0; i < 24; ++i) p.w[i] = (const float*)d_in[1 + i];

    lstm_kernel<<<NCTA, 128>>>(p);
    proj_kernel<<<(B_ + 127) / 128, 128>>>((const float*)d_in[25],
                                           (const float*)d_in[26],
                                           (float*)d_out);
}

// round 7
// speedup vs baseline: 1.5138x; 1.5138x over previous
#include <cuda_runtime.h>

// LSTM_74122545594502: 3-layer bidirectional LSTM, B=4096 T=256 D=4 H=16.
// Round 7: round-6 intra-warp layer skew (iteration K computes gates of
// L1(step K), L2(step K-1), L3(step K-2) concurrently; 1 syncwarp/iter)
// with the round-6 bias bug FIXED: per-row duplicated bias pairs
// (a00/a01 <- (b_r0,b_r0), a10/a11 <- (b_r1,b_r1)), as validated in round 4.

namespace {
constexpr int B_ = 4096;
constexpr int T_ = 256;
constexpr int D_ = 4;
constexpr int H_ = 16;
constexpr int NB = 4;                      // chains per warp
constexpr int WPC = 4;                     // warps per CTA
constexpr int NCTA = 2 * (B_ / NB) / WPC;  // 512
constexpr int WPITCH = 36;                 // smem weight row pitch (floats)
}

typedef unsigned long long ull;

__device__ __forceinline__ ull pack2(float x, float y) {
    ull r;
    asm("mov.b64 %0, {%1, %2};" : "=l"(r) : "f"(x), "f"(y));
    return r;
}
__device__ __forceinline__ void unpack2(ull v, float& x, float& y) {
    asm("mov.b64 {%0, %1}, %2;" : "=f"(x), "=f"(y) : "l"(v));
}
__device__ __forceinline__ ull ffma2(ull a, ull b, ull c) {
    ull d;
    asm("fma.rn.f32x2 %0, %1, %2, %3;" : "=l"(d) : "l"(a), "l"(b), "l"(c));
    return d;
}
__device__ __forceinline__ ull mul2(ull a, ull b) {
    ull d;
    asm("mul.rn.f32x2 %0, %1, %2;" : "=l"(d) : "l"(a), "l"(b));
    return d;
}

// sigmoid(v) = 1/(1+exp(-v)); tanh(v) = 2*sigmoid(2v)-1.
__device__ __forceinline__ float fast_act(float v, bool is_tanh) {
    float arg = is_tanh ? (-2.0f * v) : (-v);
    float e = __expf(arg);
    float r = __fdividef(1.0f, 1.0f + e);
    return is_tanh ? (2.0f * r - 1.0f) : r;
}
__device__ __forceinline__ float fast_tanh(float v) { return fast_act(v, true); }

struct Params {
    const float* y;
    const float* w[24];  // dir*12 + {Wih1,Whh1,bih1,bhh1, Wih2,...,bhh3}
};

__device__ float g_h3[2][B_][H_];  // final layer-3 h

// One input index j: wp0/wp1 = duplicated weights of rows r0/r1;
// v = chain-pair inputs (c0,c1),(c2,c3).
__device__ __forceinline__ void gstep(ull wp0, ull wp1, ulonglong2 v,
                                      ull& a00, ull& a01, ull& a10, ull& a11) {
    a00 = ffma2(wp0, v.x, a00);
    a01 = ffma2(wp0, v.y, a01);
    a10 = ffma2(wp1, v.x, a10);
    a11 = ffma2(wp1, v.y, a11);
}

// Layer-1 gates: register weights. a00/a01 carry row r0 (bias bplo),
// a10/a11 carry row r1 (bias bphi).
__device__ __forceinline__ void gates_l1(
    const ulonglong2* xv, const ulonglong2* hv,
    const float* wi0, const float* wi1, const float* wh0, const float* wh1,
    ull bplo, ull bphi, ull& a00, ull& a01, ull& a10, ull& a11)
{
    a00 = bplo; a01 = bplo; a10 = bphi; a11 = bphi;
#pragma unroll
    for (int j = 0; j < D_; ++j)
        gstep(pack2(wi0[j], wi0[j]), pack2(wi1[j], wi1[j]), xv[j],
              a00, a01, a10, a11);
#pragma unroll
    for (int j = 0; j < H_; ++j)
        gstep(pack2(wh0[j], wh0[j]), pack2(wh1[j], wh1[j]), hv[j],
              a00, a01, a10, a11);
}

// Layer-2/3 gates: scalar weights from smem.
__device__ __forceinline__ void gates_l23(
    const float (*wsmL)[WPITCH], int r0, int r1,
    const ulonglong2* inA, const ulonglong2* inB,
    ull bplo, ull bphi, ull& a00, ull& a01, ull& a10, ull& a11)
{
    a00 = bplo; a01 = bplo; a10 = bphi; a11 = bphi;
#pragma unroll
    for (int jq = 0; jq < 4; ++jq) {
        float4 w0 = *(const float4*)&wsmL[r0][4 * jq];
        float4 w1 = *(const float4*)&wsmL[r1][4 * jq];
        gstep(pack2(w0.x, w0.x), pack2(w1.x, w1.x), inA[4 * jq + 0], a00, a01, a10, a11);
        gstep(pack2(w0.y, w0.y), pack2(w1.y, w1.y), inA[4 * jq + 1], a00, a01, a10, a11);
        gstep(pack2(w0.z, w0.z), pack2(w1.z, w1.z), inA[4 * jq + 2], a00, a01, a10, a11);
        gstep(pack2(w0.w, w0.w), pack2(w1.w, w1.w), inA[4 * jq + 3], a00, a01, a10, a11);
    }
#pragma unroll
    for (int jq = 4; jq < 8; ++jq) {
        float4 w0 = *(const float4*)&wsmL[r0][4 * jq];
        float4 w1 = *(const float4*)&wsmL[r1][4 * jq];
        gstep(pack2(w0.x, w0.x), pack2(w1.x, w1.x), inB[4 * jq - 16], a00, a01, a10, a11);
        gstep(pack2(w0.y, w0.y), pack2(w1.y, w1.y), inB[4 * jq - 15], a00, a01, a10, a11);
        gstep(pack2(w0.z, w0.z), pack2(w1.z, w1.z), inB[4 * jq - 14], a00, a01, a10, a11);
        gstep(pack2(w0.w, w0.w), pack2(w1.w, w1.w), inB[4 * jq - 13], a00, a01, a10, a11);
    }
}

// Activate + bfly(16) exchange + c/h update (round-4 validated).
__device__ __forceinline__ ull do_update(ull a00, ull a01, ull a10, ull a11,
                                         bool low, float& cA, float& cB,
                                         float* hdst) {
    float p0, p1, p2, p3, q0, q1, q2, q3;
    unpack2(a00, p0, p1); unpack2(a01, p2, p3);
    unpack2(a10, q0, q1); unpack2(a11, q2, q3);
    p0 = fast_act(p0, false); p1 = fast_act(p1, false);
    p2 = fast_act(p2, false); p3 = fast_act(p3, false);
    q0 = fast_act(q0, low);   q1 = fast_act(q1, low);
    q2 = fast_act(q2, low);   q3 = fast_act(q3, low);
    ull A01 = pack2(p0, p1), A23 = pack2(p2, p3);
    ull B01 = pack2(q0, q1), B23 = pack2(q2, q3);
    ull sA = low ? A23 : A01;
    ull sB = low ? B23 : B01;
    ull rA = __shfl_xor_sync(0xffffffffu, sA, 16);
    ull rB = __shfl_xor_sync(0xffffffffu, sB, 16);
    ull I = low ? A01 : rA;
    ull F = low ? rA : A23;
    ull G = low ? B01 : rB;
    ull O = low ? rB : B23;
    ull cp = pack2(cA, cB);
    cp = ffma2(F, cp, mul2(I, G));
    unpack2(cp, cA, cB);
    float o0, o1;
    unpack2(O, o0, o1);
    ull hv = pack2(o0 * fast_tanh(cA), o1 * fast_tanh(cB));
    *(ull*)hdst = hv;
    return hv;
}

__global__ void __launch_bounds__(128, 4) lstm_kernel(Params p) {
    __shared__ float  wsm[2][64][WPITCH];   // L2/L3 weights [layer][row][ih|hh]
    __shared__ float4 xs[WPC][2][D_];       // [warp][buf][j] = 4 chains
    __shared__ float4 hs[WPC][3][2][H_];    // [warp][layer][buf][unit] = 4 chains

    const int tid  = threadIdx.x;
    const int lane = tid & 31;
    const int w    = tid >> 5;
    const int dir  = blockIdx.x >> 8;
    const int gidx = (blockIdx.x & 255) * WPC + w;
    const int b0   = gidx * NB;
    const bool low = lane < 16;
    const int unit = lane & 15;

    const float* const* ws = &p.w[dir * 12];

    // ---- cooperative fill of L2/L3 weight table ----
    for (int i = tid; i < 2 * 64 * 32; i += 128) {
        int layer = i >> 11, rem = i & 2047, row = rem >> 5, col = rem & 31;
        float v = (col < 16) ? ws[4 + layer * 4][row * 16 + col]
                             : ws[5 + layer * 4][row * 16 + (col - 16)];
        wsm[layer][row][col] = v;
    }

    // ---- L1 weights + biases in registers (per-row duplicated biases!) ----
    const int r0 = lane, r1 = lane + 32;
    float wi0[D_], wi1[D_], wh0[H_], wh1[H_];
#pragma unroll
    for (int j = 0; j < D_; ++j) { wi0[j] = ws[0][r0 * D_ + j]; wi1[j] = ws[0][r1 * D_ + j]; }
#pragma unroll
    for (int j = 0; j < H_; ++j) { wh0[j] = ws[1][r0 * H_ + j]; wh1[j] = ws[1][r1 * H_ + j]; }
    const float b1l = ws[2][r0] + ws[3][r0],  b1h = ws[2][r1] + ws[3][r1];
    const float b2l = ws[6][r0] + ws[7][r0],  b2h = ws[6][r1] + ws[7][r1];
    const float b3l = ws[10][r0] + ws[11][r0], b3h = ws[10][r1] + ws[11][r1];
    const ull bp1l = pack2(b1l, b1l), bp1h = pack2(b1h, b1h);
    const ull bp2l = pack2(b2l, b2l), bp2h = pack2(b2h, b2h);
    const ull bp3l = pack2(b3l, b3l), bp3h = pack2(b3h, b3h);

    // ---- init: BOTH h buffers zero; x buffer 0 = x[step 0] ----
    const int xc = lane >> 2, xj = lane & 3;  // low lanes: chain, component
    if (low) {
        float4 z = make_float4(0.f, 0.f, 0.f, 0.f);
#pragma unroll
        for (int bb = 0; bb < 2; ++bb) {
            hs[w][0][bb][unit] = z; hs[w][1][bb][unit] = z; hs[w][2][bb][unit] = z;
        }
        int tt = dir ? (T_ - 1) : 0;
        ((float*)&xs[w][0][xj])[xc] = p.y[((size_t)(b0 + xc) * T_ + tt) * D_ + xj];
    }
    __syncthreads();  // weight table + init visible

    float c1A = 0.f, c1B = 0.f, c2A = 0.f, c2B = 0.f, c3A = 0.f, c3B = 0.f;
    ull h3out = 0ull;
    const int hoff = low ? 0 : 2;

    // Iteration K: gates of L1(step K), L2(step K-1), L3(step K-2); reads
    // from buffer rb=K&1, writes to wb=rb^1. U1/U2/U3 enable the updates.
#define ITER(K, U1, U2, U3) do {                                              \
    const int rb_ = (K) & 1, wb_ = rb_ ^ 1;                                   \
    float xn_ = 0.f;                                                          \
    if (low) {                                                                \
        int tt_ = dir ? (T_ - 2 - (K)) : ((K) + 1);                           \
        tt_ = tt_ < 0 ? 0 : (tt_ > T_ - 1 ? T_ - 1 : tt_);                    \
        xn_ = p.y[((size_t)(b0 + xc) * T_ + tt_) * D_ + xj];                  \
    }                                                                         \
    ull A0, A1, A2, A3, B0, B1, B2, B3, C0, C1, C2, C3;                       \
    gates_l1((const ulonglong2*)&xs[w][rb_][0],                               \
             (const ulonglong2*)&hs[w][0][rb_][0],                            \
             wi0, wi1, wh0, wh1, bp1l, bp1h, A0, A1, A2, A3);                 \
    gates_l23(wsm[0], r0, r1,                                                 \
              (const ulonglong2*)&hs[w][0][rb_][0],                           \
              (const ulonglong2*)&hs[w][1][rb_][0],                           \
              bp2l, bp2h, B0, B1, B2, B3);                                    \
    gates_l23(wsm[1], r0, r1,                                                 \
              (const ulonglong2*)&hs[w][1][rb_][0],                           \
              (const ulonglong2*)&hs[w][2][rb_][0],                           \
              bp3l, bp3h, C0, C1, C2, C3);                                    \
    if (U1) do_update(A0, A1, A2, A3, low, c1A, c1B,                          \
                      (float*)&hs[w][0][wb_][unit] + hoff);                   \
    if (U2) do_update(B0, B1, B2, B3, low, c2A, c2B,                          \
                      (float*)&hs[w][1][wb_][unit] + hoff);                   \
    if (U3) h3out = do_update(C0, C1, C2, C3, low, c3A, c3B,                  \
                              (float*)&hs[w][2][wb_][unit] + hoff);           \
    if (low) ((float*)&xs[w][wb_][xj])[xc] = xn_;                             \
    __syncwarp();                                                             \
} while (0)

    ITER(0, true, false, false);
    ITER(1, true, true, false);
#pragma unroll 1
    for (int k = 2; k < T_; ++k) ITER(k, true, true, true);
    ITER(T_, false, true, true);
    ITER(T_ + 1, false, false, true);
#undef ITER

    // final layer-3 h (step T-1): low lane -> chains 0,1; high -> 2,3.
    {
        float ha, hb;
        unpack2(h3out, ha, hb);
        int c = low ? 0 : 2;
        g_h3[dir][b0 + c][unit]     = ha;
        g_h3[dir][b0 + c + 1][unit] = hb;
    }
}

// out[b,k] = b_out[k] + sum_j W_out[k][j]*hf3[b][j] + W_out[k][16+j]*hb3[b][j]
__global__ void proj_kernel(const float* __restrict__ Wo,
                            const float* __restrict__ bo,
                            float* __restrict__ out) {
    int b = blockIdx.x * blockDim.x + threadIdx.x;
    if (b >= B_) return;
    float a0 = bo[0], a1 = bo[1], a2 = bo[2], a3 = bo[3];
#pragma unroll
    for (int j = 0; j < H_; ++j) {
        float hf = g_h3[0][b][j];
        a0 += Wo[0 * 32 + j] * hf;
        a1 += Wo[1 * 32 + j] * hf;
        a2 += Wo[2 * 32 + j] * hf;
        a3 += Wo[3 * 32 + j] * hf;
    }
#pragma unroll
    for (int j = 0; j < H_; ++j) {
        float hb = g_h3[1][b][j];
        a0 += Wo[0 * 32 + 16 + j] * hb;
        a1 += Wo[1 * 32 + 16 + j] * hb;
        a2 += Wo[2 * 32 + 16 + j] * hb;
        a3 += Wo[3 * 32 + 16 + j] * hb;
    }
    ((float4*)out)[b] = make_float4(a0, a1, a2, a3);
}

extern "C" void kernel_launch(void* const* d_in, const int* in_sizes, int n_in,
                              void* d_out, int out_size) {
    (void)in_sizes; (void)n_in; (void)out_size;
    Params p;
    p.y = (const float*)d_in[0];
    for (int i = 0; i < 24; ++i) p.w[i] = (const float*)d_in[1 + i];

    lstm_kernel<<<NCTA, 128>>>(p);
    proj_kernel<<<(B_ + 127) / 128, 128>>>((const float*)d_in[25],
                                           (const float*)d_in[26],
                                           (float*)d_out);
}

// round 8
// speedup vs baseline: 1.6003x; 1.0571x over previous
#include <cuda_runtime.h>

// LSTM_74122545594502: 3-layer bidirectional LSTM, B=4096 T=256 D=4 H=16.
// Round 8: round-7 skewed warp-synchronous design, NB 4 -> 8 chains/warp to
// amortize per-warp weight reload (LDS + MOV-dup are per-warp fixed costs).
// 1024 warps total, 256 CTAs x 128 thr. Lane l owns gate rows (l, l+32);
// chain pairs packed in f32x2: A[0..3]=row r0 x 8 chains, B[0..3]=row r1.
// Iteration K computes L1(K), L2(K-1), L3(K-2); 1 syncwarp/iter.

namespace {
constexpr int B_ = 4096;
constexpr int T_ = 256;
constexpr int D_ = 4;
constexpr int H_ = 16;
constexpr int NB = 8;                      // chains per warp
constexpr int WPC = 4;                     // warps per CTA
constexpr int NCTA = 2 * (B_ / NB) / WPC;  // 256
constexpr int WPITCH = 36;                 // smem weight row pitch (floats)
}

typedef unsigned long long ull;

__device__ __forceinline__ ull pack2(float x, float y) {
    ull r;
    asm("mov.b64 %0, {%1, %2};" : "=l"(r) : "f"(x), "f"(y));
    return r;
}
__device__ __forceinline__ void unpack2(ull v, float& x, float& y) {
    asm("mov.b64 {%0, %1}, %2;" : "=f"(x), "=f"(y) : "l"(v));
}
__device__ __forceinline__ ull ffma2(ull a, ull b, ull c) {
    ull d;
    asm("fma.rn.f32x2 %0, %1, %2, %3;" : "=l"(d) : "l"(a), "l"(b), "l"(c));
    return d;
}
__device__ __forceinline__ ull mul2(ull a, ull b) {
    ull d;
    asm("mul.rn.f32x2 %0, %1, %2;" : "=l"(d) : "l"(a), "l"(b));
    return d;
}

// sigmoid(v) = 1/(1+exp(-v)); tanh(v) = 2*sigmoid(2v)-1.
__device__ __forceinline__ float fast_act(float v, bool is_tanh) {
    float arg = is_tanh ? (-2.0f * v) : (-v);
    float e = __expf(arg);
    float r = __fdividef(1.0f, 1.0f + e);
    return is_tanh ? (2.0f * r - 1.0f) : r;
}
__device__ __forceinline__ float fast_tanh(float v) { return fast_act(v, true); }

struct Params {
    const float* y;
    const float* w[24];  // dir*12 + {Wih1,Whh1,bih1,bhh1, Wih2,...,bhh3}
};

__device__ float g_h3[2][B_][H_];  // final layer-3 h

// One input index j: 2 broadcast LDS.128 feed 8 FFMA2 (8 chains, 2 rows).
__device__ __forceinline__ void gstep8(ull wp0, ull wp1, const float* vj,
                                       ull* A, ull* B) {
    ulonglong2 v01 = *(const ulonglong2*)(vj);
    ulonglong2 v23 = *(const ulonglong2*)(vj + 4);
    A[0] = ffma2(wp0, v01.x, A[0]);
    A[1] = ffma2(wp0, v01.y, A[1]);
    A[2] = ffma2(wp0, v23.x, A[2]);
    A[3] = ffma2(wp0, v23.y, A[3]);
    B[0] = ffma2(wp1, v01.x, B[0]);
    B[1] = ffma2(wp1, v01.y, B[1]);
    B[2] = ffma2(wp1, v23.x, B[2]);
    B[3] = ffma2(wp1, v23.y, B[3]);
}

// Layer-1 gates: register weights. A rows carry r0 (bias bplo), B rows r1.
__device__ __forceinline__ void gates_l1(
    const float* xin, const float* hin,
    const float* wi0, const float* wi1, const float* wh0, const float* wh1,
    ull bplo, ull bphi, ull* A, ull* B)
{
#pragma unroll
    for (int k = 0; k < 4; ++k) { A[k] = bplo; B[k] = bphi; }
#pragma unroll
    for (int j = 0; j < D_; ++j)
        gstep8(pack2(wi0[j], wi0[j]), pack2(wi1[j], wi1[j]), xin + 8 * j, A, B);
#pragma unroll
    for (int j = 0; j < H_; ++j)
        gstep8(pack2(wh0[j], wh0[j]), pack2(wh1[j], wh1[j]), hin + 8 * j, A, B);
}

// Layer-2/3 gates: scalar weights from smem (float4 loads + MOV dup).
__device__ __forceinline__ void gates_l23(
    const float (*wsmL)[WPITCH], int r0, int r1,
    const float* inA, const float* inB,
    ull bplo, ull bphi, ull* A, ull* B)
{
#pragma unroll
    for (int k = 0; k < 4; ++k) { A[k] = bplo; B[k] = bphi; }
#pragma unroll
    for (int jq = 0; jq < 4; ++jq) {
        float4 w0 = *(const float4*)&wsmL[r0][4 * jq];
        float4 w1 = *(const float4*)&wsmL[r1][4 * jq];
        gstep8(pack2(w0.x, w0.x), pack2(w1.x, w1.x), inA + 8 * (4 * jq + 0), A, B);
        gstep8(pack2(w0.y, w0.y), pack2(w1.y, w1.y), inA + 8 * (4 * jq + 1), A, B);
        gstep8(pack2(w0.z, w0.z), pack2(w1.z, w1.z), inA + 8 * (4 * jq + 2), A, B);
        gstep8(pack2(w0.w, w0.w), pack2(w1.w, w1.w), inA + 8 * (4 * jq + 3), A, B);
    }
#pragma unroll
    for (int jq = 4; jq < 8; ++jq) {
        float4 w0 = *(const float4*)&wsmL[r0][4 * jq];
        float4 w1 = *(const float4*)&wsmL[r1][4 * jq];
        gstep8(pack2(w0.x, w0.x), pack2(w1.x, w1.x), inB + 8 * (4 * jq - 16), A, B);
        gstep8(pack2(w0.y, w0.y), pack2(w1.y, w1.y), inB + 8 * (4 * jq - 15), A, B);
        gstep8(pack2(w0.z, w0.z), pack2(w1.z, w1.z), inB + 8 * (4 * jq - 14), A, B);
        gstep8(pack2(w0.w, w0.w), pack2(w1.w, w1.w), inB + 8 * (4 * jq - 13), A, B);
    }
}

// Activate + bfly(16) exchange + c/h update for 8 chains.
// Low lane ends with chains 0-3 of its unit; high lane chains 4-7.
__device__ __forceinline__ float4 do_update8(ull* A, ull* B, bool low,
                                             ull& c0, ull& c1, float* hdst) {
    float af[8], bf[8];
#pragma unroll
    for (int k = 0; k < 4; ++k) {
        unpack2(A[k], af[2 * k], af[2 * k + 1]);
        unpack2(B[k], bf[2 * k], bf[2 * k + 1]);
    }
#pragma unroll
    for (int i = 0; i < 8; ++i) {
        af[i] = fast_act(af[i], false);   // i (low) / f (high): sigmoid
        bf[i] = fast_act(bf[i], low);     // g (low): tanh; o (high): sigmoid
    }
#pragma unroll
    for (int k = 0; k < 4; ++k) {
        A[k] = pack2(af[2 * k], af[2 * k + 1]);
        B[k] = pack2(bf[2 * k], bf[2 * k + 1]);
    }
    ull s0 = low ? A[2] : A[0];
    ull s1 = low ? A[3] : A[1];
    ull s2 = low ? B[2] : B[0];
    ull s3 = low ? B[3] : B[1];
    ull r0 = __shfl_xor_sync(0xffffffffu, s0, 16);
    ull r1 = __shfl_xor_sync(0xffffffffu, s1, 16);
    ull r2 = __shfl_xor_sync(0xffffffffu, s2, 16);
    ull r3 = __shfl_xor_sync(0xffffffffu, s3, 16);
    ull I0 = low ? A[0] : r0, I1 = low ? A[1] : r1;
    ull F0 = low ? r0 : A[2], F1 = low ? r1 : A[3];
    ull G0 = low ? B[0] : r2, G1 = low ? B[1] : r3;
    ull O0 = low ? r2 : B[2], O1 = low ? r3 : B[3];
    c0 = ffma2(F0, c0, mul2(I0, G0));
    c1 = ffma2(F1, c1, mul2(I1, G1));
    float ca0, ca1, ca2, ca3, o0, o1, o2, o3;
    unpack2(c0, ca0, ca1);
    unpack2(c1, ca2, ca3);
    unpack2(O0, o0, o1);
    unpack2(O1, o2, o3);
    float4 h = make_float4(o0 * fast_tanh(ca0), o1 * fast_tanh(ca1),
                           o2 * fast_tanh(ca2), o3 * fast_tanh(ca3));
    *(float4*)hdst = h;
    return h;
}

__global__ void __launch_bounds__(128, 2) lstm_kernel(Params p) {
    __shared__ float wsm[2][64][WPITCH];    // L2/L3 weights [layer][row][ih|hh]
    __shared__ __align__(16) float xs[WPC][2][D_][NB];     // x per warp
    __shared__ __align__(16) float hs[WPC][3][2][H_][NB];  // h per warp/layer

    const int tid  = threadIdx.x;
    const int lane = tid & 31;
    const int w    = tid >> 5;
    const int dir  = blockIdx.x >> 7;                // 128 CTAs per dir
    const int gidx = (blockIdx.x & 127) * WPC + w;   // 0..511 per dir
    const int b0   = gidx * NB;
    const bool low = lane < 16;
    const int unit = lane & 15;

    const float* const* ws = &p.w[dir * 12];

    // ---- cooperative fill of L2/L3 weight table ----
    for (int i = tid; i < 2 * 64 * 32; i += 128) {
        int layer = i >> 11, rem = i & 2047, row = rem >> 5, col = rem & 31;
        float v = (col < 16) ? ws[4 + layer * 4][row * 16 + col]
                             : ws[5 + layer * 4][row * 16 + (col - 16)];
        wsm[layer][row][col] = v;
    }

    // ---- L1 weights + per-row duplicated biases in registers ----
    const int r0 = lane, r1 = lane + 32;
    float wi0[D_], wi1[D_], wh0[H_], wh1[H_];
#pragma unroll
    for (int j = 0; j < D_; ++j) { wi0[j] = ws[0][r0 * D_ + j]; wi1[j] = ws[0][r1 * D_ + j]; }
#pragma unroll
    for (int j = 0; j < H_; ++j) { wh0[j] = ws[1][r0 * H_ + j]; wh1[j] = ws[1][r1 * H_ + j]; }
    const float b1l = ws[2][r0] + ws[3][r0],   b1h = ws[2][r1] + ws[3][r1];
    const float b2l = ws[6][r0] + ws[7][r0],   b2h = ws[6][r1] + ws[7][r1];
    const float b3l = ws[10][r0] + ws[11][r0], b3h = ws[10][r1] + ws[11][r1];
    const ull bp1l = pack2(b1l, b1l), bp1h = pack2(b1h, b1h);
    const ull bp2l = pack2(b2l, b2l), bp2h = pack2(b2h, b2h);
    const ull bp3l = pack2(b3l, b3l), bp3h = pack2(b3h, b3h);

    // ---- init: both h buffers zero; x buffer 0 = x[step 0] ----
    {
        float4* hp = (float4*)&hs[w][0][0][0][0];
#pragma unroll
        for (int i = lane; i < 3 * 2 * H_ * NB / 4; i += 32)
            hp[i] = make_float4(0.f, 0.f, 0.f, 0.f);
    }
    const int xc = lane >> 2, xj = lane & 3;  // chain 0..7, component 0..3
    {
        int tt = dir ? (T_ - 1) : 0;
        xs[w][0][xj][xc] = p.y[((size_t)(b0 + xc) * T_ + tt) * D_ + xj];
    }
    __syncthreads();  // weight table + buffers visible

    ull c1p0 = 0ull, c1p1 = 0ull, c2p0 = 0ull, c2p1 = 0ull, c3p0 = 0ull, c3p1 = 0ull;
    float4 h3f = make_float4(0.f, 0.f, 0.f, 0.f);
    const int hoff = low ? 0 : 4;

    // Iteration K: gates of L1(step K), L2(step K-1), L3(step K-2); reads
    // buffer rb=K&1, writes wb=rb^1. U1/U2/U3 enable the updates.
#define ITER(K, U1, U2, U3) do {                                              \
    const int rb_ = (K) & 1, wb_ = rb_ ^ 1;                                   \
    int tt_ = dir ? (T_ - 2 - (K)) : ((K) + 1);                               \
    tt_ = tt_ < 0 ? 0 : (tt_ > T_ - 1 ? T_ - 1 : tt_);                        \
    float xn_ = p.y[((size_t)(b0 + xc) * T_ + tt_) * D_ + xj];                \
    ull A1_[4], B1_[4], A2_[4], B2_[4], A3_[4], B3_[4];                       \
    gates_l1(&xs[w][rb_][0][0], &hs[w][0][rb_][0][0],                         \
             wi0, wi1, wh0, wh1, bp1l, bp1h, A1_, B1_);                       \
    gates_l23(wsm[0], r0, r1,                                                 \
              &hs[w][0][rb_][0][0], &hs[w][1][rb_][0][0],                     \
              bp2l, bp2h, A2_, B2_);                                          \
    gates_l23(wsm[1], r0, r1,                                                 \
              &hs[w][1][rb_][0][0], &hs[w][2][rb_][0][0],                     \
              bp3l, bp3h, A3_, B3_);                                          \
    if (U1) do_update8(A1_, B1_, low, c1p0, c1p1,                             \
                       &hs[w][0][wb_][unit][0] + hoff);                       \
    if (U2) do_update8(A2_, B2_, low, c2p0, c2p1,                             \
                       &hs[w][1][wb_][unit][0] + hoff);                       \
    if (U3) h3f = do_update8(A3_, B3_, low, c3p0, c3p1,                       \
                             &hs[w][2][wb_][unit][0] + hoff);                 \
    xs[w][wb_][xj][xc] = xn_;                                                 \
    __syncwarp();                                                             \
} while (0)

    ITER(0, true, false, false);
    ITER(1, true, true, false);
#pragma unroll 1
    for (int k = 2; k < T_; ++k) ITER(k, true, true, true);
    ITER(T_, false, true, true);
    ITER(T_ + 1, false, false, true);
#undef ITER

    // final layer-3 h (step T-1): low lane -> chains 0-3; high -> 4-7.
    {
        int cb = b0 + (low ? 0 : 4);
        g_h3[dir][cb + 0][unit] = h3f.x;
        g_h3[dir][cb + 1][unit] = h3f.y;
        g_h3[dir][cb + 2][unit] = h3f.z;
        g_h3[dir][cb + 3][unit] = h3f.w;
    }
}

// out[b,k] = b_out[k] + sum_j W_out[k][j]*hf3[b][j] + W_out[k][16+j]*hb3[b][j]
__global__ void proj_kernel(const float* __restrict__ Wo,
                            const float* __restrict__ bo,
                            float* __restrict__ out) {
    int b = blockIdx.x * blockDim.x + threadIdx.x;
    if (b >= B_) return;
    float a0 = bo[0], a1 = bo[1], a2 = bo[2], a3 = bo[3];
#pragma unroll
    for (int j = 0; j < H_; ++j) {
        float hf = g_h3[0][b][j];
        a0 += Wo[0 * 32 + j] * hf;
        a1 += Wo[1 * 32 + j] * hf;
        a2 += Wo[2 * 32 + j] * hf;
        a3 += Wo[3 * 32 + j] * hf;
    }
#pragma unroll
    for (int j = 0; j < H_; ++j) {
        float hb = g_h3[1][b][j];
        a0 += Wo[0 * 32 + 16 + j] * hb;
        a1 += Wo[1 * 32 + 16 + j] * hb;
        a2 += Wo[2 * 32 + 16 + j] * hb;
        a3 += Wo[3 * 32 + 16 + j] * hb;
    }
    ((float4*)out)[b] = make_float4(a0, a1, a2, a3);
}

extern "C" void kernel_launch(void* const* d_in, const int* in_sizes, int n_in,
                              void* d_out, int out_size) {
    (void)in_sizes; (void)n_in; (void)out_size;
    Params p;
    p.y = (const float*)d_in[0];
    for (int i = 0; i < 24; ++i) p.w[i] = (const float*)d_in[1 + i];

    lstm_kernel<<<NCTA, 128>>>(p);
    proj_kernel<<<(B_ + 127) / 128, 128>>>((const float*)d_in[25],
                                           (const float*)d_in[26],
                                           (float*)d_out);
}